// round 12
// baseline (speedup 1.0000x reference)
#include <cuda_runtime.h>
#include <math.h>

#define B_ 8
#define T_ 1024
#define C_ 32
#define F_ 256
#define D_ 128
#define K_ 512
#define Q_ (B_*T_)      // 8192
#define KCH 32          // k per CTA chunk
#define NKC (K_/KCH)    // 16
#define QT 64
#define NQT (Q_/QT)     // 128
#define NREP 4          // G atomic replicas

// ---------------- scratch (no allocations allowed) ----------------
__device__ float g_bd[NKC*Q_];
__device__ int   g_bi[NKC*Q_];
__device__ float g_E[Q_*C_];
__device__ float g_Gr[NREP*C_*F_];
__device__ float g_S[F_];
__device__ float g_acc[2];        // [0] = sum E^2, [1] = sum (h-z)^2
__device__ unsigned int g_done;   // last-CTA counter (self-resetting)

#define ABSMASK 0x7fffffff7fffffffULL

__device__ __forceinline__ unsigned long long fadd2u(unsigned long long a,
                                                     unsigned long long b) {
    unsigned long long r;
    asm("add.rn.f32x2 %0, %1, %2;" : "=l"(r) : "l"(a), "l"(b));
    return r;
}

// ---------------- zero accumulators ----------------
__global__ void zero_kernel() {
    int g = blockIdx.x * 256 + threadIdx.x;
    if (g < NREP*C_*F_) g_Gr[g] = 0.f;
    if (g < F_)         g_S[g] = 0.f;
    if (g < 2)          g_acc[g] = 0.f;
}

// ---------------- L1 NN search: m-dup packing + 2-stage pipeline -----------
// 2048 CTAs (128 q-tiles x 16 k-chunks), 256 threads. CTA = 64 q x 32 k.
// smem: h plain [128][64] 32KB + m duplicated (m,m) [128][64] 32KB -> 3 CTA/SM.
// Thread = 4q x 2k. Per d: 2 LDS.128 + 4 fadd2 diff + 8 LOP3 + 4 fadd2 acc
//   = 1.0 fma + 1.0 alu + 2.25 issue per element. No MOVs: h comes packed
//   (q0,q1),(q2,q3); m comes packed (m,m) from smem.
__global__ void __launch_bounds__(256, 3)
nn7_kernel(const float* __restrict__ H, const float* __restrict__ M) {
    extern __shared__ char smem[];
    float* h_s = (float*)smem;                 // [128][64] plain
    float* m_s = (float*)(smem + 32*1024);     // [128][64] = 32 k dup'd

    int tid = threadIdx.x;
    int qt = blockIdx.x & (NQT - 1);
    int kc = blockIdx.x >> 7;
    int q0 = qt * QT;
    int b  = q0 >> 10;
    int t0 = q0 & (T_ - 1);
    int k0 = kc * KCH;

    for (int e = tid; e < (D_*QT)/4; e += 256) {
        int d = e >> 4, q4 = e & 15;
        *(float4*)&h_s[d*QT + q4*4] =
            *(const float4*)&H[b*(D_*T_) + d*T_ + t0 + q4*4];
    }
    for (int e = tid; e < D_*KCH; e += 256) {
        int d = e >> 5, j = e & 31;
        float v = -M[d*K_ + k0 + j];
        *(float2*)&m_s[d*64 + j*2] = make_float2(v, v);
    }
    __syncthreads();

    int tk = tid & 15, tq = tid >> 4;   // 16 k-lanes x 16 q-groups
    int qq = tq * 4, kk4 = tk * 4;      // both LDS.128 conflict-free

    unsigned long long a00=0ULL, a01=0ULL, a10=0ULL, a11=0ULL;
    // 2-stage software pipeline: prefetch d+1 while computing d
    ulonglong2 hh = *(const ulonglong2*)&h_s[qq];       // (h0,h1),(h2,h3)
    ulonglong2 mm = *(const ulonglong2*)&m_s[kk4];      // (-m0,-m0),(-m1,-m1)
    #pragma unroll 4
    for (int d = 0; d < D_ - 1; d++) {
        ulonglong2 hn = *(const ulonglong2*)&h_s[(d+1)*QT + qq];
        ulonglong2 mn = *(const ulonglong2*)&m_s[(d+1)*64 + kk4];
        a00 = fadd2u(a00, fadd2u(hh.x, mm.x) & ABSMASK);
        a01 = fadd2u(a01, fadd2u(hh.x, mm.y) & ABSMASK);
        a10 = fadd2u(a10, fadd2u(hh.y, mm.x) & ABSMASK);
        a11 = fadd2u(a11, fadd2u(hh.y, mm.y) & ABSMASK);
        hh = hn; mm = mn;
    }
    a00 = fadd2u(a00, fadd2u(hh.x, mm.x) & ABSMASK);
    a01 = fadd2u(a01, fadd2u(hh.x, mm.y) & ABSMASK);
    a10 = fadd2u(a10, fadd2u(hh.y, mm.x) & ABSMASK);
    a11 = fadd2u(a11, fadd2u(hh.y, mm.y) & ABSMASK);

    // unpack: a00=(q0,q1)@k0  a01=(q0,q1)@k1  a10=(q2,q3)@k0  a11=(q2,q3)@k1
    int kb = k0 + tk*2;
    float bd[4]; int bi[4];
    {
        float c0 = __uint_as_float((unsigned)(a00 & 0xffffffffu));   // q0@k0
        float c1 = __uint_as_float((unsigned)(a01 & 0xffffffffu));   // q0@k1
        bd[0] = c0; bi[0] = kb;
        if (c1 < bd[0]) { bd[0] = c1; bi[0] = kb + 1; }
        c0 = __uint_as_float((unsigned)(a00 >> 32));                 // q1@k0
        c1 = __uint_as_float((unsigned)(a01 >> 32));                 // q1@k1
        bd[1] = c0; bi[1] = kb;
        if (c1 < bd[1]) { bd[1] = c1; bi[1] = kb + 1; }
        c0 = __uint_as_float((unsigned)(a10 & 0xffffffffu));         // q2@k0
        c1 = __uint_as_float((unsigned)(a11 & 0xffffffffu));         // q2@k1
        bd[2] = c0; bi[2] = kb;
        if (c1 < bd[2]) { bd[2] = c1; bi[2] = kb + 1; }
        c0 = __uint_as_float((unsigned)(a10 >> 32));                 // q3@k0
        c1 = __uint_as_float((unsigned)(a11 >> 32));                 // q3@k1
        bd[3] = c0; bi[3] = kb;
        if (c1 < bd[3]) { bd[3] = c1; bi[3] = kb + 1; }
    }

    // lexicographic min across the 16 tk lanes (first-argmin semantics)
    #pragma unroll
    for (int off = 1; off < 16; off <<= 1) {
        #pragma unroll
        for (int iq = 0; iq < 4; iq++) {
            float od = __shfl_xor_sync(0xffffffffu, bd[iq], off);
            int   oi = __shfl_xor_sync(0xffffffffu, bi[iq], off);
            if (od < bd[iq] || (od == bd[iq] && oi < bi[iq])) { bd[iq] = od; bi[iq] = oi; }
        }
    }
    if (tk == 0) {
        #pragma unroll
        for (int iq = 0; iq < 4; iq++) {
            g_bd[kc*Q_ + q0 + qq + iq] = bd[iq];
            g_bi[kc*Q_ + q0 + qq + iq] = bi[iq];
        }
    }
}

// ---------------- combine K-chunks + quantization loss + FUSED final -------
// 32 CTAs x 256 threads; last CTA to finish performs the scalar assembly.
__global__ void nnred_final_kernel(const float* __restrict__ H, const float* __restrict__ M,
                                   const float* __restrict__ W, const float* __restrict__ w_d,
                                   float* __restrict__ out) {
    __shared__ float red[8];
    __shared__ unsigned int is_last;
    int tid = threadIdx.x;
    int q = blockIdx.x * 256 + tid;
    float bd = g_bd[q]; int bi = g_bi[q];
    #pragma unroll
    for (int c = 1; c < NKC; c++) {
        float dd = g_bd[c*Q_ + q]; int ii = g_bi[c*Q_ + q];
        if (dd < bd) { bd = dd; bi = ii; }   // chunks ascend in k
    }
    int b = q >> 10, t = q & (T_ - 1);
    const float* h = H + b*(D_*T_) + t;
    float s = 0.f;
    #pragma unroll 8
    for (int d = 0; d < D_; d++) {
        float diff = h[d*T_] - M[d*K_ + bi];
        s += diff * diff;
    }
    #pragma unroll
    for (int off = 16; off > 0; off >>= 1) s += __shfl_down_sync(0xffffffffu, s, off);
    int warp = tid >> 5, lane = tid & 31;
    if (lane == 0) red[warp] = s;
    __syncthreads();
    if (tid == 0) {
        float tot = 0.f;
        #pragma unroll
        for (int i = 0; i < 8; i++) tot += red[i];
        atomicAdd(&g_acc[1], tot);
        __threadfence();
        unsigned int v = atomicAdd(&g_done, 1);
        is_last = (v == gridDim.x - 1) ? 1u : 0u;
    }
    __syncthreads();
    if (!is_last) return;

    // ---- final scalar assembly (this CTA only; all other CTAs' atomics visible) ----
    __shared__ float4 red4[8];
    float sG = 0.f, sWS = 0.f;
    for (int i = tid; i < C_*F_; i += 256) {
        float g = g_Gr[i] + g_Gr[C_*F_ + i] + g_Gr[2*C_*F_ + i] + g_Gr[3*C_*F_ + i];
        sG  += g * g;
        sWS += W[i] * g_S[i & 255] * w_d[i >> 8];
    }
    float sv  = g_S[tid];          // F_ == 256 == blockDim
    float sS  = sv * sv;
    float wd2 = (tid < C_) ? w_d[tid]*w_d[tid] : 0.f;

    #pragma unroll
    for (int off = 16; off > 0; off >>= 1) {
        sG  += __shfl_down_sync(0xffffffffu, sG,  off);
        sWS += __shfl_down_sync(0xffffffffu, sWS, off);
        sS  += __shfl_down_sync(0xffffffffu, sS,  off);
        wd2 += __shfl_down_sync(0xffffffffu, wd2, off);
    }
    if (lane == 0) red4[warp] = make_float4(sG, sWS, sS, wd2);
    __syncthreads();
    if (tid == 0) {
        float4 v = make_float4(0.f, 0.f, 0.f, 0.f);
        #pragma unroll
        for (int i = 0; i < 8; i++) {
            v.x += red4[i].x; v.y += red4[i].y; v.z += red4[i].z; v.w += red4[i].w;
        }
        float loss_rec = g_acc[0] / 262144.f;                 // mean over B*T*C
        float loss_m   = 2.f * g_acc[1] / 1048576.f;          // 2*sum/(B*D*T)
        float normGrec = (2.f / 262144.f) * sqrtf(v.x);       // ||g_rec||_F
        float normGd   = sqrtf(v.w) * sqrtf(v.z) / 8192.f;    // ||g_d||_F (rank-1)
        float lmbda    = normGrec / (normGd + 1e-6f);
        float loss_d   = -v.y / 8192.f;
        out[0] = loss_rec + loss_m + lmbda * loss_d;
        g_done = 0;                                           // self-reset for replay
    }
}

// ---------------- dec_e: E = Hdec W^T - X -> g_E (STG), sumE^2 -------------
__global__ void dece_kernel(const float* __restrict__ Hdec, const float* __restrict__ W,
                            const float* __restrict__ X) {
    extern __shared__ char smem[];
    float* hd_s = (float*)smem;                // [16][256]  16KB
    float* w_s  = (float*)(smem + 16384);      // [256][33]  33KB padded
    __shared__ float red[8];

    int tid = threadIdx.x;
    int r0 = blockIdx.x * 16;
    int warp = tid >> 5, lane = tid & 31;

    for (int e = tid; e < C_*F_; e += 256) {
        int c = e >> 8, f = e & 255;
        w_s[f*33 + c] = W[e];
    }
    {
        const float4* src = (const float4*)(Hdec + (size_t)r0 * F_);
        float4* dst = (float4*)hd_s;
        #pragma unroll
        for (int i = 0; i < 4; i++) dst[tid + i*256] = src[tid + i*256];
    }
    __syncthreads();

    float acc0 = 0.f, acc1 = 0.f;
    for (int f = 0; f < F_; f += 4) {
        float w0 = w_s[(f+0)*33 + lane];
        float w1 = w_s[(f+1)*33 + lane];
        float w2 = w_s[(f+2)*33 + lane];
        float w3 = w_s[(f+3)*33 + lane];
        float4 a4 = *(const float4*)&hd_s[(warp*2    )*F_ + f];
        float4 b4 = *(const float4*)&hd_s[(warp*2 + 1)*F_ + f];
        acc0 = fmaf(a4.x, w0, fmaf(a4.y, w1, fmaf(a4.z, w2, fmaf(a4.w, w3, acc0))));
        acc1 = fmaf(b4.x, w0, fmaf(b4.y, w1, fmaf(b4.z, w2, fmaf(b4.w, w3, acc1))));
    }
    float e0 = acc0 - X[(size_t)(r0 + warp*2    )*C_ + lane];
    float e1 = acc1 - X[(size_t)(r0 + warp*2 + 1)*C_ + lane];
    g_E[(r0 + warp*2    )*C_ + lane] = e0;
    g_E[(r0 + warp*2 + 1)*C_ + lane] = e1;
    float s2 = e0*e0 + e1*e1;
    #pragma unroll
    for (int off = 16; off > 0; off >>= 1) s2 += __shfl_down_sync(0xffffffffu, s2, off);
    if (lane == 0) red[warp] = s2;
    __syncthreads();
    if (tid == 0) {
        float tot = 0.f;
        #pragma unroll
        for (int i = 0; i < 8; i++) tot += red[i];
        atomicAdd(&g_acc[0], tot);
    }
}

// ---------------- dec_g: G = E^T @ Hdec (tiled GEMM) + S partials ----------
__global__ void decg_kernel(const float* __restrict__ Hdec) {
    __shared__ float e_s[64*32];    //  8KB
    __shared__ float hd_s[64*64];   // 16KB
    int tid = threadIdx.x;
    int rc = blockIdx.x & 63, ft = blockIdx.x >> 6;
    int r0 = rc * 128, f0 = ft * 64;
    int tc = tid & 15, tf = tid >> 4;

    float ga[8] = {0,0,0,0,0,0,0,0};
    float scol = 0.f;

    for (int sub = 0; sub < 2; sub++) {
        int rr0 = r0 + sub*64;
        __syncthreads();
        {
            const float4* esrc = (const float4*)(g_E + (size_t)rr0 * C_);
            float4* edst = (float4*)e_s;
            edst[tid]       = esrc[tid];
            edst[tid + 256] = esrc[tid + 256];
            const float4* hsrc = (const float4*)(Hdec + (size_t)rr0 * F_ + f0);
            float4* hdst = (float4*)hd_s;
            #pragma unroll
            for (int i = 0; i < 4; i++) {
                int idx = tid + i*256;
                int row = idx >> 4, c4 = idx & 15;
                hdst[row*16 + c4] = hsrc[row*64 + c4];
            }
        }
        __syncthreads();
        #pragma unroll 4
        for (int r = 0; r < 64; r++) {
            float2 ec = *(const float2*)&e_s[r*32 + tc*2];
            float4 hv = *(const float4*)&hd_s[r*64 + tf*4];
            ga[0] += ec.x*hv.x; ga[1] += ec.x*hv.y; ga[2] += ec.x*hv.z; ga[3] += ec.x*hv.w;
            ga[4] += ec.y*hv.x; ga[5] += ec.y*hv.y; ga[6] += ec.y*hv.z; ga[7] += ec.y*hv.w;
        }
        if (tid < 64) {
            #pragma unroll 8
            for (int r = 0; r < 64; r++) scol += hd_s[r*64 + tid];
        }
    }

    if (tid < 64) atomicAdd(&g_S[f0 + tid], scol);
    float* gdst = &g_Gr[(rc & (NREP-1))*C_*F_];
    int c0 = tc*2, fbase = f0 + tf*4;
    #pragma unroll
    for (int j = 0; j < 4; j++) {
        atomicAdd(&gdst[(c0    )*F_ + fbase + j], ga[j]);
        atomicAdd(&gdst[(c0 + 1)*F_ + fbase + j], ga[4 + j]);
    }
}

extern "C" void kernel_launch(void* const* d_in, const int* in_sizes, int n_in,
                              void* d_out, int out_size) {
    const float* X    = (const float*)d_in[0];
    const float* H    = (const float*)d_in[1];
    const float* M    = (const float*)d_in[2];
    const float* Hdec = (const float*)d_in[3];
    const float* W    = (const float*)d_in[4];
    const float* w_d  = (const float*)d_in[5];
    float* out = (float*)d_out;
    (void)in_sizes; (void)n_in; (void)out_size;

    static int init_done = 0;
    static cudaStream_t s2;
    static cudaEvent_t ev_fork, ev_join;
    if (!init_done) {
        cudaFuncSetAttribute(nn7_kernel,  cudaFuncAttributeMaxDynamicSharedMemorySize, 65536);
        cudaFuncSetAttribute(dece_kernel, cudaFuncAttributeMaxDynamicSharedMemorySize, 50176);
        cudaStreamCreateWithFlags(&s2, cudaStreamNonBlocking);
        cudaEventCreateWithFlags(&ev_fork, cudaEventDisableTiming);
        cudaEventCreateWithFlags(&ev_join, cudaEventDisableTiming);
        init_done = 1;
    }

    // fork: decoder chain on s2 overlaps the NN chain on the capture stream
    cudaEventRecord(ev_fork, 0);
    cudaStreamWaitEvent(s2, ev_fork, 0);

    zero_kernel <<<(NREP*C_*F_ + 255)/256, 256, 0, s2>>>();
    dece_kernel <<<Q_/16, 256, 50176, s2>>>(Hdec, W, X);   // 512 CTAs
    decg_kernel <<<256, 256, 0, s2>>>(Hdec);               // 256 CTAs

    nn7_kernel  <<<NQT*NKC, 256, 65536>>>(H, M);           // 2048 CTAs: hot kernel

    // join BEFORE the fused nnred+final (its final phase reads s2 results)
    cudaEventRecord(ev_join, s2);
    cudaStreamWaitEvent(0, ev_join, 0);
    nnred_final_kernel<<<Q_/256, 256>>>(H, M, W, w_d, out);
}

// round 13
// speedup vs baseline: 1.2551x; 1.2551x over previous
#include <cuda_runtime.h>
#include <math.h>

#define B_ 8
#define T_ 1024
#define C_ 32
#define F_ 256
#define D_ 128
#define K_ 512
#define Q_ (B_*T_)      // 8192
#define KCH 64          // k per CTA chunk
#define NKC (K_/KCH)    // 8
#define QT 64
#define NQT (Q_/QT)     // 128
#define NREP 4          // G atomic replicas

// ---------------- scratch (no allocations allowed) ----------------
__device__ float g_bd[NKC*Q_];
__device__ int   g_bi[NKC*Q_];
__device__ float g_E[Q_*C_];
__device__ float g_Gr[NREP*C_*F_];
__device__ float g_S[F_];
__device__ float g_acc[2];        // [0] = sum E^2, [1] = sum (h-z)^2
__device__ unsigned int g_done;   // last-CTA counter (self-resetting)

#define ABSMASK 0x7fffffff7fffffffULL

__device__ __forceinline__ unsigned long long fadd2u(unsigned long long a,
                                                     unsigned long long b) {
    unsigned long long r;
    asm("add.rn.f32x2 %0, %1, %2;" : "=l"(r) : "l"(a), "l"(b));
    return r;
}

__device__ __forceinline__ unsigned long long dupf(float v) {
    float2 p = make_float2(v, v);
    return reinterpret_cast<unsigned long long&>(p);
}

// ---------------- zero accumulators ----------------
__global__ void zero_kernel() {
    int g = blockIdx.x * 256 + threadIdx.x;
    if (g < NREP*C_*F_) g_Gr[g] = 0.f;
    if (g < F_)         g_S[g] = 0.f;
    if (g < 2)          g_acc[g] = 0.f;
}

// ---------------- L1 NN search: nn6 shape + explicit 2-stage pipeline ------
// 1024 CTAs (128 q-tiles x 8 k-chunks), 256 threads. CTA = 64 q x 64 k.
// smem: h plain [128][64] 32KB + m negated [128][64] 32KB = 64KB -> 3 CTA/SM.
// Thread = 4q x 4k. Per d: 2 LDS.128 + 4 MOV + 8 fadd2 diff + 16 LOP3 + 8 fadd2 acc.
// Prefetch d+1's h/m into regs while computing d -> LDS latency hidden.
__global__ void __launch_bounds__(256, 3)
nn8_kernel(const float* __restrict__ H, const float* __restrict__ M) {
    extern __shared__ char smem[];
    float* h_s = (float*)smem;                 // [128][64] plain
    float* m_s = (float*)(smem + 32*1024);     // [128][64] negated

    int tid = threadIdx.x;
    int qt = blockIdx.x & (NQT - 1);
    int kc = blockIdx.x >> 7;
    int q0 = qt * QT;
    int b  = q0 >> 10;
    int t0 = q0 & (T_ - 1);
    int k0 = kc * KCH;

    for (int e = tid; e < (D_*QT)/4; e += 256) {
        int d = e >> 4, q4 = e & 15;
        *(float4*)&h_s[d*QT + q4*4] =
            *(const float4*)&H[b*(D_*T_) + d*T_ + t0 + q4*4];
    }
    for (int e = tid; e < (D_*KCH)/4; e += 256) {
        int d = e >> 4, c4 = e & 15;
        float4 mv = *(const float4*)&M[d*K_ + k0 + c4*4];
        *(float4*)&m_s[d*KCH + c4*4] = make_float4(-mv.x, -mv.y, -mv.z, -mv.w);
    }
    __syncthreads();

    int tk = tid & 15, tq = tid >> 4;   // 16 k-groups x 16 q-groups
    int qq = tq * 4, kk = tk * 4;       // both LDS.128 conflict-free

    unsigned long long a00=0ULL,a01=0ULL,a10=0ULL,a11=0ULL;
    unsigned long long a20=0ULL,a21=0ULL,a30=0ULL,a31=0ULL;

    // 2-stage pipeline: hv/mm hold iteration d; hn/mn prefetch d+1
    float4 hv = *(const float4*)&h_s[qq];
    ulonglong2 mm = *(const ulonglong2*)&m_s[kk];
    #pragma unroll 4
    for (int d = 0; d < D_ - 1; d++) {
        float4 hn = *(const float4*)&h_s[(d+1)*QT + qq];
        ulonglong2 mn = *(const ulonglong2*)&m_s[(d+1)*KCH + kk];
        unsigned long long H0 = dupf(hv.x), H1 = dupf(hv.y);
        unsigned long long H2 = dupf(hv.z), H3 = dupf(hv.w);
        a00 = fadd2u(a00, fadd2u(H0, mm.x) & ABSMASK);
        a01 = fadd2u(a01, fadd2u(H0, mm.y) & ABSMASK);
        a10 = fadd2u(a10, fadd2u(H1, mm.x) & ABSMASK);
        a11 = fadd2u(a11, fadd2u(H1, mm.y) & ABSMASK);
        a20 = fadd2u(a20, fadd2u(H2, mm.x) & ABSMASK);
        a21 = fadd2u(a21, fadd2u(H2, mm.y) & ABSMASK);
        a30 = fadd2u(a30, fadd2u(H3, mm.x) & ABSMASK);
        a31 = fadd2u(a31, fadd2u(H3, mm.y) & ABSMASK);
        hv = hn; mm = mn;
    }
    {
        unsigned long long H0 = dupf(hv.x), H1 = dupf(hv.y);
        unsigned long long H2 = dupf(hv.z), H3 = dupf(hv.w);
        a00 = fadd2u(a00, fadd2u(H0, mm.x) & ABSMASK);
        a01 = fadd2u(a01, fadd2u(H0, mm.y) & ABSMASK);
        a10 = fadd2u(a10, fadd2u(H1, mm.x) & ABSMASK);
        a11 = fadd2u(a11, fadd2u(H1, mm.y) & ABSMASK);
        a20 = fadd2u(a20, fadd2u(H2, mm.x) & ABSMASK);
        a21 = fadd2u(a21, fadd2u(H2, mm.y) & ABSMASK);
        a30 = fadd2u(a30, fadd2u(H3, mm.x) & ABSMASK);
        a31 = fadd2u(a31, fadd2u(H3, mm.y) & ABSMASK);
    }

    // thread-local lexmin per q over its 4 k (ascending k, strict <)
    int kb = k0 + kk;
    float bd[4]; int bi[4];
    unsigned long long p0[4] = {a00, a10, a20, a30};
    unsigned long long p1[4] = {a01, a11, a21, a31};
    #pragma unroll
    for (int iq = 0; iq < 4; iq++) {
        float c0 = __uint_as_float((unsigned)(p0[iq] & 0xffffffffu));
        float c1 = __uint_as_float((unsigned)(p0[iq] >> 32));
        float c2 = __uint_as_float((unsigned)(p1[iq] & 0xffffffffu));
        float c3 = __uint_as_float((unsigned)(p1[iq] >> 32));
        float bdv = c0; int biv = kb;
        if (c1 < bdv) { bdv = c1; biv = kb + 1; }
        if (c2 < bdv) { bdv = c2; biv = kb + 2; }
        if (c3 < bdv) { bdv = c3; biv = kb + 3; }
        bd[iq] = bdv; bi[iq] = biv;
    }

    // lexicographic min across the 16 tk lanes (first-argmin semantics)
    #pragma unroll
    for (int off = 1; off < 16; off <<= 1) {
        #pragma unroll
        for (int iq = 0; iq < 4; iq++) {
            float od = __shfl_xor_sync(0xffffffffu, bd[iq], off);
            int   oi = __shfl_xor_sync(0xffffffffu, bi[iq], off);
            if (od < bd[iq] || (od == bd[iq] && oi < bi[iq])) { bd[iq] = od; bi[iq] = oi; }
        }
    }
    if (tk == 0) {
        #pragma unroll
        for (int iq = 0; iq < 4; iq++) {
            g_bd[kc*Q_ + q0 + qq + iq] = bd[iq];
            g_bi[kc*Q_ + q0 + qq + iq] = bi[iq];
        }
    }
}

// ---------------- combine K-chunks + quantization loss + FUSED final -------
// 32 CTAs x 256 threads; last CTA to finish performs the scalar assembly.
__global__ void nnred_final_kernel(const float* __restrict__ H, const float* __restrict__ M,
                                   const float* __restrict__ W, const float* __restrict__ w_d,
                                   float* __restrict__ out) {
    __shared__ float red[8];
    __shared__ unsigned int is_last;
    int tid = threadIdx.x;
    int q = blockIdx.x * 256 + tid;
    float bd = g_bd[q]; int bi = g_bi[q];
    #pragma unroll
    for (int c = 1; c < NKC; c++) {
        float dd = g_bd[c*Q_ + q]; int ii = g_bi[c*Q_ + q];
        if (dd < bd) { bd = dd; bi = ii; }   // chunks ascend in k
    }
    int b = q >> 10, t = q & (T_ - 1);
    const float* h = H + b*(D_*T_) + t;
    float s = 0.f;
    #pragma unroll 8
    for (int d = 0; d < D_; d++) {
        float diff = h[d*T_] - M[d*K_ + bi];
        s += diff * diff;
    }
    #pragma unroll
    for (int off = 16; off > 0; off >>= 1) s += __shfl_down_sync(0xffffffffu, s, off);
    int warp = tid >> 5, lane = tid & 31;
    if (lane == 0) red[warp] = s;
    __syncthreads();
    if (tid == 0) {
        float tot = 0.f;
        #pragma unroll
        for (int i = 0; i < 8; i++) tot += red[i];
        atomicAdd(&g_acc[1], tot);
        __threadfence();
        unsigned int v = atomicAdd(&g_done, 1);
        is_last = (v == gridDim.x - 1) ? 1u : 0u;
    }
    __syncthreads();
    if (!is_last) return;

    // ---- final scalar assembly (last CTA; all other CTAs' atomics visible) ----
    __shared__ float4 red4[8];
    float sG = 0.f, sWS = 0.f;
    for (int i = tid; i < C_*F_; i += 256) {
        float g = g_Gr[i] + g_Gr[C_*F_ + i] + g_Gr[2*C_*F_ + i] + g_Gr[3*C_*F_ + i];
        sG  += g * g;
        sWS += W[i] * g_S[i & 255] * w_d[i >> 8];
    }
    float sv  = g_S[tid];          // F_ == 256 == blockDim
    float sS  = sv * sv;
    float wd2 = (tid < C_) ? w_d[tid]*w_d[tid] : 0.f;

    #pragma unroll
    for (int off = 16; off > 0; off >>= 1) {
        sG  += __shfl_down_sync(0xffffffffu, sG,  off);
        sWS += __shfl_down_sync(0xffffffffu, sWS, off);
        sS  += __shfl_down_sync(0xffffffffu, sS,  off);
        wd2 += __shfl_down_sync(0xffffffffu, wd2, off);
    }
    if (lane == 0) red4[warp] = make_float4(sG, sWS, sS, wd2);
    __syncthreads();
    if (tid == 0) {
        float4 v = make_float4(0.f, 0.f, 0.f, 0.f);
        #pragma unroll
        for (int i = 0; i < 8; i++) {
            v.x += red4[i].x; v.y += red4[i].y; v.z += red4[i].z; v.w += red4[i].w;
        }
        float loss_rec = g_acc[0] / 262144.f;                 // mean over B*T*C
        float loss_m   = 2.f * g_acc[1] / 1048576.f;          // 2*sum/(B*D*T)
        float normGrec = (2.f / 262144.f) * sqrtf(v.x);       // ||g_rec||_F
        float normGd   = sqrtf(v.w) * sqrtf(v.z) / 8192.f;    // ||g_d||_F (rank-1)
        float lmbda    = normGrec / (normGd + 1e-6f);
        float loss_d   = -v.y / 8192.f;
        out[0] = loss_rec + loss_m + lmbda * loss_d;
        g_done = 0;                                           // self-reset for replay
    }
}

// ---------------- dec_e: E = Hdec W^T - X -> g_E (STG), sumE^2 -------------
__global__ void dece_kernel(const float* __restrict__ Hdec, const float* __restrict__ W,
                            const float* __restrict__ X) {
    extern __shared__ char smem[];
    float* hd_s = (float*)smem;                // [16][256]  16KB
    float* w_s  = (float*)(smem + 16384);      // [256][33]  33KB padded
    __shared__ float red[8];

    int tid = threadIdx.x;
    int r0 = blockIdx.x * 16;
    int warp = tid >> 5, lane = tid & 31;

    for (int e = tid; e < C_*F_; e += 256) {
        int c = e >> 8, f = e & 255;
        w_s[f*33 + c] = W[e];
    }
    {
        const float4* src = (const float4*)(Hdec + (size_t)r0 * F_);
        float4* dst = (float4*)hd_s;
        #pragma unroll
        for (int i = 0; i < 4; i++) dst[tid + i*256] = src[tid + i*256];
    }
    __syncthreads();

    float acc0 = 0.f, acc1 = 0.f;
    for (int f = 0; f < F_; f += 4) {
        float w0 = w_s[(f+0)*33 + lane];
        float w1 = w_s[(f+1)*33 + lane];
        float w2 = w_s[(f+2)*33 + lane];
        float w3 = w_s[(f+3)*33 + lane];
        float4 a4 = *(const float4*)&hd_s[(warp*2    )*F_ + f];
        float4 b4 = *(const float4*)&hd_s[(warp*2 + 1)*F_ + f];
        acc0 = fmaf(a4.x, w0, fmaf(a4.y, w1, fmaf(a4.z, w2, fmaf(a4.w, w3, acc0))));
        acc1 = fmaf(b4.x, w0, fmaf(b4.y, w1, fmaf(b4.z, w2, fmaf(b4.w, w3, acc1))));
    }
    float e0 = acc0 - X[(size_t)(r0 + warp*2    )*C_ + lane];
    float e1 = acc1 - X[(size_t)(r0 + warp*2 + 1)*C_ + lane];
    g_E[(r0 + warp*2    )*C_ + lane] = e0;
    g_E[(r0 + warp*2 + 1)*C_ + lane] = e1;
    float s2 = e0*e0 + e1*e1;
    #pragma unroll
    for (int off = 16; off > 0; off >>= 1) s2 += __shfl_down_sync(0xffffffffu, s2, off);
    if (lane == 0) red[warp] = s2;
    __syncthreads();
    if (tid == 0) {
        float tot = 0.f;
        #pragma unroll
        for (int i = 0; i < 8; i++) tot += red[i];
        atomicAdd(&g_acc[0], tot);
    }
}

// ---------------- dec_g: G = E^T @ Hdec (tiled GEMM) + S partials ----------
__global__ void decg_kernel(const float* __restrict__ Hdec) {
    __shared__ float e_s[64*32];    //  8KB
    __shared__ float hd_s[64*64];   // 16KB
    int tid = threadIdx.x;
    int rc = blockIdx.x & 63, ft = blockIdx.x >> 6;
    int r0 = rc * 128, f0 = ft * 64;
    int tc = tid & 15, tf = tid >> 4;

    float ga[8] = {0,0,0,0,0,0,0,0};
    float scol = 0.f;

    for (int sub = 0; sub < 2; sub++) {
        int rr0 = r0 + sub*64;
        __syncthreads();
        {
            const float4* esrc = (const float4*)(g_E + (size_t)rr0 * C_);
            float4* edst = (float4*)e_s;
            edst[tid]       = esrc[tid];
            edst[tid + 256] = esrc[tid + 256];
            const float4* hsrc = (const float4*)(Hdec + (size_t)rr0 * F_ + f0);
            float4* hdst = (float4*)hd_s;
            #pragma unroll
            for (int i = 0; i < 4; i++) {
                int idx = tid + i*256;
                int row = idx >> 4, c4 = idx & 15;
                hdst[row*16 + c4] = hsrc[row*64 + c4];
            }
        }
        __syncthreads();
        #pragma unroll 4
        for (int r = 0; r < 64; r++) {
            float2 ec = *(const float2*)&e_s[r*32 + tc*2];
            float4 hv = *(const float4*)&hd_s[r*64 + tf*4];
            ga[0] += ec.x*hv.x; ga[1] += ec.x*hv.y; ga[2] += ec.x*hv.z; ga[3] += ec.x*hv.w;
            ga[4] += ec.y*hv.x; ga[5] += ec.y*hv.y; ga[6] += ec.y*hv.z; ga[7] += ec.y*hv.w;
        }
        if (tid < 64) {
            #pragma unroll 8
            for (int r = 0; r < 64; r++) scol += hd_s[r*64 + tid];
        }
    }

    if (tid < 64) atomicAdd(&g_S[f0 + tid], scol);
    float* gdst = &g_Gr[(rc & (NREP-1))*C_*F_];
    int c0 = tc*2, fbase = f0 + tf*4;
    #pragma unroll
    for (int j = 0; j < 4; j++) {
        atomicAdd(&gdst[(c0    )*F_ + fbase + j], ga[j]);
        atomicAdd(&gdst[(c0 + 1)*F_ + fbase + j], ga[4 + j]);
    }
}

extern "C" void kernel_launch(void* const* d_in, const int* in_sizes, int n_in,
                              void* d_out, int out_size) {
    const float* X    = (const float*)d_in[0];
    const float* H    = (const float*)d_in[1];
    const float* M    = (const float*)d_in[2];
    const float* Hdec = (const float*)d_in[3];
    const float* W    = (const float*)d_in[4];
    const float* w_d  = (const float*)d_in[5];
    float* out = (float*)d_out;
    (void)in_sizes; (void)n_in; (void)out_size;

    static int init_done = 0;
    static cudaStream_t s2;
    static cudaEvent_t ev_fork, ev_join;
    if (!init_done) {
        cudaFuncSetAttribute(nn8_kernel,  cudaFuncAttributeMaxDynamicSharedMemorySize, 65536);
        cudaFuncSetAttribute(dece_kernel, cudaFuncAttributeMaxDynamicSharedMemorySize, 50176);
        cudaStreamCreateWithFlags(&s2, cudaStreamNonBlocking);
        cudaEventCreateWithFlags(&ev_fork, cudaEventDisableTiming);
        cudaEventCreateWithFlags(&ev_join, cudaEventDisableTiming);
        init_done = 1;
    }

    // fork: decoder chain on s2 overlaps the NN chain on the capture stream
    cudaEventRecord(ev_fork, 0);
    cudaStreamWaitEvent(s2, ev_fork, 0);

    zero_kernel <<<(NREP*C_*F_ + 255)/256, 256, 0, s2>>>();
    dece_kernel <<<Q_/16, 256, 50176, s2>>>(Hdec, W, X);   // 512 CTAs
    decg_kernel <<<256, 256, 0, s2>>>(Hdec);               // 256 CTAs

    nn8_kernel  <<<NQT*NKC, 256, 65536>>>(H, M);           // 1024 CTAs: hot kernel

    // join BEFORE the fused nnred+final (its final phase reads s2 results)
    cudaEventRecord(ev_join, s2);
    cudaStreamWaitEvent(0, ev_join, 0);
    nnred_final_kernel<<<Q_/256, 256>>>(H, M, W, w_d, out);
}

// round 14
// speedup vs baseline: 1.2828x; 1.0220x over previous
#include <cuda_runtime.h>
#include <math.h>

#define B_ 8
#define T_ 1024
#define C_ 32
#define F_ 256
#define D_ 128
#define K_ 512
#define Q_ (B_*T_)      // 8192
#define KCH 64          // k per CTA chunk
#define NKC (K_/KCH)    // 8
#define QT 64
#define NQT (Q_/QT)     // 128
#define NREP 4          // G atomic replicas

// ---------------- scratch (no allocations allowed) ----------------
__device__ float g_bd[NKC*Q_];
__device__ int   g_bi[NKC*Q_];
__device__ float g_E[Q_*C_];
__device__ float g_Gr[NREP*C_*F_];
__device__ float g_S[F_];
__device__ float g_acc[2];           // [0] = sum E^2 ([1] unused now)
__device__ float g_qpart[NQT];       // per-q-tile sum (h-z)^2 (plain stores)
__device__ unsigned int g_cnt[NQT];  // per-q-tile arrival counters (self-resetting)

#define ABSMASK 0x7fffffff7fffffffULL

__device__ __forceinline__ unsigned long long fadd2u(unsigned long long a,
                                                     unsigned long long b) {
    unsigned long long r;
    asm("add.rn.f32x2 %0, %1, %2;" : "=l"(r) : "l"(a), "l"(b));
    return r;
}

__device__ __forceinline__ unsigned long long dupf(float v) {
    float2 p = make_float2(v, v);
    return reinterpret_cast<unsigned long long&>(p);
}

// ---------------- zero accumulators (decoder-side only) ----------------
__global__ void zero_kernel() {
    int g = blockIdx.x * 256 + threadIdx.x;
    if (g < NREP*C_*F_) g_Gr[g] = 0.f;
    if (g < F_)         g_S[g] = 0.f;
    if (g < 2)          g_acc[g] = 0.f;
}

// ---------------- L1 NN search + in-kernel per-q-tile combine --------------
// 1024 CTAs (128 q-tiles x 8 k-chunks), 256 threads. CTA = 64 q x 64 k.
// Main loop identical to nn8 (R13). After the chunk result is written, the
// LAST chunk-CTA of each q-tile combines all 8 candidates and computes the
// quantization loss using its own h_s copy; stores to g_qpart[qt].
__global__ void __launch_bounds__(256, 3)
nn9_kernel(const float* __restrict__ H, const float* __restrict__ M) {
    extern __shared__ char smem[];
    float* h_s = (float*)smem;                 // [128][64] plain
    float* m_s = (float*)(smem + 32*1024);     // [128][64] negated

    __shared__ unsigned int lastf;
    __shared__ float qred[2];

    int tid = threadIdx.x;
    int qt = blockIdx.x & (NQT - 1);
    int kc = blockIdx.x >> 7;
    int q0 = qt * QT;
    int b  = q0 >> 10;
    int t0 = q0 & (T_ - 1);
    int k0 = kc * KCH;

    for (int e = tid; e < (D_*QT)/4; e += 256) {
        int d = e >> 4, q4 = e & 15;
        *(float4*)&h_s[d*QT + q4*4] =
            *(const float4*)&H[b*(D_*T_) + d*T_ + t0 + q4*4];
    }
    for (int e = tid; e < (D_*KCH)/4; e += 256) {
        int d = e >> 4, c4 = e & 15;
        float4 mv = *(const float4*)&M[d*K_ + k0 + c4*4];
        *(float4*)&m_s[d*KCH + c4*4] = make_float4(-mv.x, -mv.y, -mv.z, -mv.w);
    }
    __syncthreads();

    int tk = tid & 15, tq = tid >> 4;   // 16 k-groups x 16 q-groups
    int qq = tq * 4, kk = tk * 4;       // both LDS.128 conflict-free

    unsigned long long a00=0ULL,a01=0ULL,a10=0ULL,a11=0ULL;
    unsigned long long a20=0ULL,a21=0ULL,a30=0ULL,a31=0ULL;

    // 2-stage pipeline: hv/mm hold iteration d; hn/mn prefetch d+1
    float4 hv = *(const float4*)&h_s[qq];
    ulonglong2 mm = *(const ulonglong2*)&m_s[kk];
    #pragma unroll 4
    for (int d = 0; d < D_ - 1; d++) {
        float4 hn = *(const float4*)&h_s[(d+1)*QT + qq];
        ulonglong2 mn = *(const ulonglong2*)&m_s[(d+1)*KCH + kk];
        unsigned long long H0 = dupf(hv.x), H1 = dupf(hv.y);
        unsigned long long H2 = dupf(hv.z), H3 = dupf(hv.w);
        a00 = fadd2u(a00, fadd2u(H0, mm.x) & ABSMASK);
        a01 = fadd2u(a01, fadd2u(H0, mm.y) & ABSMASK);
        a10 = fadd2u(a10, fadd2u(H1, mm.x) & ABSMASK);
        a11 = fadd2u(a11, fadd2u(H1, mm.y) & ABSMASK);
        a20 = fadd2u(a20, fadd2u(H2, mm.x) & ABSMASK);
        a21 = fadd2u(a21, fadd2u(H2, mm.y) & ABSMASK);
        a30 = fadd2u(a30, fadd2u(H3, mm.x) & ABSMASK);
        a31 = fadd2u(a31, fadd2u(H3, mm.y) & ABSMASK);
        hv = hn; mm = mn;
    }
    {
        unsigned long long H0 = dupf(hv.x), H1 = dupf(hv.y);
        unsigned long long H2 = dupf(hv.z), H3 = dupf(hv.w);
        a00 = fadd2u(a00, fadd2u(H0, mm.x) & ABSMASK);
        a01 = fadd2u(a01, fadd2u(H0, mm.y) & ABSMASK);
        a10 = fadd2u(a10, fadd2u(H1, mm.x) & ABSMASK);
        a11 = fadd2u(a11, fadd2u(H1, mm.y) & ABSMASK);
        a20 = fadd2u(a20, fadd2u(H2, mm.x) & ABSMASK);
        a21 = fadd2u(a21, fadd2u(H2, mm.y) & ABSMASK);
        a30 = fadd2u(a30, fadd2u(H3, mm.x) & ABSMASK);
        a31 = fadd2u(a31, fadd2u(H3, mm.y) & ABSMASK);
    }

    // thread-local lexmin per q over its 4 k (ascending k, strict <)
    int kb = k0 + kk;
    float bd[4]; int bi[4];
    unsigned long long p0[4] = {a00, a10, a20, a30};
    unsigned long long p1[4] = {a01, a11, a21, a31};
    #pragma unroll
    for (int iq = 0; iq < 4; iq++) {
        float c0 = __uint_as_float((unsigned)(p0[iq] & 0xffffffffu));
        float c1 = __uint_as_float((unsigned)(p0[iq] >> 32));
        float c2 = __uint_as_float((unsigned)(p1[iq] & 0xffffffffu));
        float c3 = __uint_as_float((unsigned)(p1[iq] >> 32));
        float bdv = c0; int biv = kb;
        if (c1 < bdv) { bdv = c1; biv = kb + 1; }
        if (c2 < bdv) { bdv = c2; biv = kb + 2; }
        if (c3 < bdv) { bdv = c3; biv = kb + 3; }
        bd[iq] = bdv; bi[iq] = biv;
    }

    // lexicographic min across the 16 tk lanes (first-argmin semantics)
    #pragma unroll
    for (int off = 1; off < 16; off <<= 1) {
        #pragma unroll
        for (int iq = 0; iq < 4; iq++) {
            float od = __shfl_xor_sync(0xffffffffu, bd[iq], off);
            int   oi = __shfl_xor_sync(0xffffffffu, bi[iq], off);
            if (od < bd[iq] || (od == bd[iq] && oi < bi[iq])) { bd[iq] = od; bi[iq] = oi; }
        }
    }
    if (tk == 0) {
        #pragma unroll
        for (int iq = 0; iq < 4; iq++) {
            g_bd[kc*Q_ + q0 + qq + iq] = bd[iq];
            g_bi[kc*Q_ + q0 + qq + iq] = bi[iq];
        }
    }

    // ---- arrival: last chunk-CTA of this q-tile does the combine ----
    __syncthreads();
    if (tid == 0) {
        __threadfence();   // publish this CTA's g_bd/g_bi before the counter bump
        lastf = (atomicAdd(&g_cnt[qt], 1u) == NKC - 1) ? 1u : 0u;
    }
    __syncthreads();
    if (!lastf) return;
    __threadfence();       // acquire: other CTAs' fenced writes now visible

    // combine 8 candidates per q (chunks ascend in k: strict < keeps lowest idx)
    if (tid < QT) {
        int q = tid;
        float bdv = g_bd[q0 + q]; int biv = g_bi[q0 + q];
        #pragma unroll
        for (int c = 1; c < NKC; c++) {
            float dd = g_bd[c*Q_ + q0 + q]; int ii = g_bi[c*Q_ + q0 + q];
            if (dd < bdv) { bdv = dd; biv = ii; }
        }
        // quantization loss from this CTA's own h_s (still intact)
        float s = 0.f;
        #pragma unroll 4
        for (int d = 0; d < D_; d++) {
            float diff = h_s[d*QT + q] - M[d*K_ + biv];
            s += diff * diff;
        }
        #pragma unroll
        for (int off = 16; off > 0; off >>= 1) s += __shfl_down_sync(0xffffffffu, s, off);
        if ((tid & 31) == 0) qred[tid >> 5] = s;
    }
    __syncthreads();
    if (tid == 0) {
        g_qpart[qt] = qred[0] + qred[1];   // plain store: no zeroing, no race
        g_cnt[qt] = 0;                     // self-reset for graph replay
    }
}

// ---------------- dec_e: E = Hdec W^T - X -> g_E (STG), sumE^2 -------------
__global__ void dece_kernel(const float* __restrict__ Hdec, const float* __restrict__ W,
                            const float* __restrict__ X) {
    extern __shared__ char smem[];
    float* hd_s = (float*)smem;                // [16][256]  16KB
    float* w_s  = (float*)(smem + 16384);      // [256][33]  33KB padded
    __shared__ float red[8];

    int tid = threadIdx.x;
    int r0 = blockIdx.x * 16;
    int warp = tid >> 5, lane = tid & 31;

    for (int e = tid; e < C_*F_; e += 256) {
        int c = e >> 8, f = e & 255;
        w_s[f*33 + c] = W[e];
    }
    {
        const float4* src = (const float4*)(Hdec + (size_t)r0 * F_);
        float4* dst = (float4*)hd_s;
        #pragma unroll
        for (int i = 0; i < 4; i++) dst[tid + i*256] = src[tid + i*256];
    }
    __syncthreads();

    float acc0 = 0.f, acc1 = 0.f;
    for (int f = 0; f < F_; f += 4) {
        float w0 = w_s[(f+0)*33 + lane];
        float w1 = w_s[(f+1)*33 + lane];
        float w2 = w_s[(f+2)*33 + lane];
        float w3 = w_s[(f+3)*33 + lane];
        float4 a4 = *(const float4*)&hd_s[(warp*2    )*F_ + f];
        float4 b4 = *(const float4*)&hd_s[(warp*2 + 1)*F_ + f];
        acc0 = fmaf(a4.x, w0, fmaf(a4.y, w1, fmaf(a4.z, w2, fmaf(a4.w, w3, acc0))));
        acc1 = fmaf(b4.x, w0, fmaf(b4.y, w1, fmaf(b4.z, w2, fmaf(b4.w, w3, acc1))));
    }
    float e0 = acc0 - X[(size_t)(r0 + warp*2    )*C_ + lane];
    float e1 = acc1 - X[(size_t)(r0 + warp*2 + 1)*C_ + lane];
    g_E[(r0 + warp*2    )*C_ + lane] = e0;
    g_E[(r0 + warp*2 + 1)*C_ + lane] = e1;
    float s2 = e0*e0 + e1*e1;
    #pragma unroll
    for (int off = 16; off > 0; off >>= 1) s2 += __shfl_down_sync(0xffffffffu, s2, off);
    if (lane == 0) red[warp] = s2;
    __syncthreads();
    if (tid == 0) {
        float tot = 0.f;
        #pragma unroll
        for (int i = 0; i < 8; i++) tot += red[i];
        atomicAdd(&g_acc[0], tot);
    }
}

// ---------------- dec_g: G = E^T @ Hdec (tiled GEMM) + S partials ----------
__global__ void decg_kernel(const float* __restrict__ Hdec) {
    __shared__ float e_s[64*32];    //  8KB
    __shared__ float hd_s[64*64];   // 16KB
    int tid = threadIdx.x;
    int rc = blockIdx.x & 63, ft = blockIdx.x >> 6;
    int r0 = rc * 128, f0 = ft * 64;
    int tc = tid & 15, tf = tid >> 4;

    float ga[8] = {0,0,0,0,0,0,0,0};
    float scol = 0.f;

    for (int sub = 0; sub < 2; sub++) {
        int rr0 = r0 + sub*64;
        __syncthreads();
        {
            const float4* esrc = (const float4*)(g_E + (size_t)rr0 * C_);
            float4* edst = (float4*)e_s;
            edst[tid]       = esrc[tid];
            edst[tid + 256] = esrc[tid + 256];
            const float4* hsrc = (const float4*)(Hdec + (size_t)rr0 * F_ + f0);
            float4* hdst = (float4*)hd_s;
            #pragma unroll
            for (int i = 0; i < 4; i++) {
                int idx = tid + i*256;
                int row = idx >> 4, c4 = idx & 15;
                hdst[row*16 + c4] = hsrc[row*64 + c4];
            }
        }
        __syncthreads();
        #pragma unroll 4
        for (int r = 0; r < 64; r++) {
            float2 ec = *(const float2*)&e_s[r*32 + tc*2];
            float4 hv = *(const float4*)&hd_s[r*64 + tf*4];
            ga[0] += ec.x*hv.x; ga[1] += ec.x*hv.y; ga[2] += ec.x*hv.z; ga[3] += ec.x*hv.w;
            ga[4] += ec.y*hv.x; ga[5] += ec.y*hv.y; ga[6] += ec.y*hv.z; ga[7] += ec.y*hv.w;
        }
        if (tid < 64) {
            #pragma unroll 8
            for (int r = 0; r < 64; r++) scol += hd_s[r*64 + tid];
        }
    }

    if (tid < 64) atomicAdd(&g_S[f0 + tid], scol);
    float* gdst = &g_Gr[(rc & (NREP-1))*C_*F_];
    int c0 = tc*2, fbase = f0 + tf*4;
    #pragma unroll
    for (int j = 0; j < 4; j++) {
        atomicAdd(&gdst[(c0    )*F_ + fbase + j], ga[j]);
        atomicAdd(&gdst[(c0 + 1)*F_ + fbase + j], ga[4 + j]);
    }
}

// ---------------- final scalar assembly (1024 threads, shuffle reduce) -----
__global__ void final_kernel(const float* __restrict__ W, const float* __restrict__ w_d,
                             float* __restrict__ out) {
    __shared__ float4 red4[32];
    __shared__ float redq[32];
    int tid = threadIdx.x, lane = tid & 31, warp = tid >> 5;

    float sG = 0.f, sWS = 0.f;
    #pragma unroll
    for (int i = tid; i < C_*F_; i += 1024) {
        float g = g_Gr[i] + g_Gr[C_*F_ + i] + g_Gr[2*C_*F_ + i] + g_Gr[3*C_*F_ + i];
        sG  += g * g;
        sWS += W[i] * g_S[i & 255] * w_d[i >> 8];
    }
    float sS  = (tid < F_)   ? g_S[tid]*g_S[tid]   : 0.f;
    float wd2 = (tid < C_)   ? w_d[tid]*w_d[tid]   : 0.f;
    float sQ  = (tid < NQT)  ? g_qpart[tid]        : 0.f;

    #pragma unroll
    for (int off = 16; off > 0; off >>= 1) {
        sG  += __shfl_down_sync(0xffffffffu, sG,  off);
        sWS += __shfl_down_sync(0xffffffffu, sWS, off);
        sS  += __shfl_down_sync(0xffffffffu, sS,  off);
        wd2 += __shfl_down_sync(0xffffffffu, wd2, off);
        sQ  += __shfl_down_sync(0xffffffffu, sQ,  off);
    }
    if (lane == 0) { red4[warp] = make_float4(sG, sWS, sS, wd2); redq[warp] = sQ; }
    __syncthreads();
    if (warp == 0) {
        float4 v = red4[lane];
        float  q = redq[lane];
        #pragma unroll
        for (int off = 16; off > 0; off >>= 1) {
            v.x += __shfl_down_sync(0xffffffffu, v.x, off);
            v.y += __shfl_down_sync(0xffffffffu, v.y, off);
            v.z += __shfl_down_sync(0xffffffffu, v.z, off);
            v.w += __shfl_down_sync(0xffffffffu, v.w, off);
            q   += __shfl_down_sync(0xffffffffu, q,   off);
        }
        if (lane == 0) {
            float loss_rec = g_acc[0] / 262144.f;                 // mean over B*T*C
            float loss_m   = 2.f * q / 1048576.f;                 // 2*sum/(B*D*T)
            float normGrec = (2.f / 262144.f) * sqrtf(v.x);       // ||g_rec||_F
            float normGd   = sqrtf(v.w) * sqrtf(v.z) / 8192.f;    // ||g_d||_F (rank-1)
            float lmbda    = normGrec / (normGd + 1e-6f);
            float loss_d   = -v.y / 8192.f;
            out[0] = loss_rec + loss_m + lmbda * loss_d;
        }
    }
}

extern "C" void kernel_launch(void* const* d_in, const int* in_sizes, int n_in,
                              void* d_out, int out_size) {
    const float* X    = (const float*)d_in[0];
    const float* H    = (const float*)d_in[1];
    const float* M    = (const float*)d_in[2];
    const float* Hdec = (const float*)d_in[3];
    const float* W    = (const float*)d_in[4];
    const float* w_d  = (const float*)d_in[5];
    float* out = (float*)d_out;
    (void)in_sizes; (void)n_in; (void)out_size;

    static int init_done = 0;
    static cudaStream_t s2;
    static cudaEvent_t ev_fork, ev_join;
    if (!init_done) {
        cudaFuncSetAttribute(nn9_kernel,  cudaFuncAttributeMaxDynamicSharedMemorySize, 65536);
        cudaFuncSetAttribute(dece_kernel, cudaFuncAttributeMaxDynamicSharedMemorySize, 50176);
        cudaStreamCreateWithFlags(&s2, cudaStreamNonBlocking);
        cudaEventCreateWithFlags(&ev_fork, cudaEventDisableTiming);
        cudaEventCreateWithFlags(&ev_join, cudaEventDisableTiming);
        init_done = 1;
    }

    // fork: decoder chain on s2 overlaps the NN chain on the capture stream
    cudaEventRecord(ev_fork, 0);
    cudaStreamWaitEvent(s2, ev_fork, 0);

    zero_kernel <<<(NREP*C_*F_ + 255)/256, 256, 0, s2>>>();
    dece_kernel <<<Q_/16, 256, 50176, s2>>>(Hdec, W, X);   // 512 CTAs
    decg_kernel <<<256, 256, 0, s2>>>(Hdec);               // 256 CTAs

    nn9_kernel  <<<NQT*NKC, 256, 65536>>>(H, M);           // 1024 CTAs: hot kernel
                                                           // (includes combine + qloss)
    // join, then the single tiny reduction
    cudaEventRecord(ev_join, s2);
    cudaStreamWaitEvent(0, ev_join, 0);
    final_kernel<<<1, 1024>>>(W, w_d, out);
}

// round 15
// speedup vs baseline: 1.3703x; 1.0683x over previous
#include <cuda_runtime.h>
#include <math.h>

#define B_ 8
#define T_ 1024
#define C_ 32
#define F_ 256
#define D_ 128
#define K_ 512
#define Q_ (B_*T_)      // 8192
#define KCH 64          // k per CTA chunk
#define NKC (K_/KCH)    // 8
#define QT 64
#define NQT (Q_/QT)     // 128
#define NREP 4          // G atomic replicas

// ---------------- scratch (no allocations allowed) ----------------
__device__ float g_bd[NKC*Q_];
__device__ int   g_bi[NKC*Q_];
__device__ float g_Mt[K_*D_];        // transposed codebook (row-contiguous per k)
__device__ float g_E[Q_*C_];
__device__ float g_Gr[NREP*C_*F_];
__device__ float g_S[F_];
__device__ float g_acc[2];           // [0] = sum E^2, [1] = sum (h-z)^2

#define ABSMASK 0x7fffffff7fffffffULL

__device__ __forceinline__ unsigned long long fadd2u(unsigned long long a,
                                                     unsigned long long b) {
    unsigned long long r;
    asm("add.rn.f32x2 %0, %1, %2;" : "=l"(r) : "l"(a), "l"(b));
    return r;
}

__device__ __forceinline__ unsigned long long dupf(float v) {
    float2 p = make_float2(v, v);
    return reinterpret_cast<unsigned long long&>(p);
}

// ---------------- zero accumulators (decoder-side only) ----------------
__global__ void zero_kernel() {
    int g = blockIdx.x * 256 + threadIdx.x;
    if (g < NREP*C_*F_) g_Gr[g] = 0.f;
    if (g < F_)         g_S[g] = 0.f;
    if (g < 2)          g_acc[g] = 0.f;
}

// ---------------- transpose M: [D][K] -> Mt [K][D] (coalesced writes) ------
__global__ void mt_kernel(const float* __restrict__ M) {
    __shared__ float tile[32][33];
    int bx = blockIdx.x & 15, by = blockIdx.x >> 4;   // 16 k-tiles x 4 d-tiles
    int k0 = bx * 32, d0 = by * 32;
    int tx = threadIdx.x & 31, ty = threadIdx.x >> 5; // 32 x 8
    #pragma unroll
    for (int i = 0; i < 4; i++)
        tile[ty + i*8][tx] = M[(d0 + ty + i*8)*K_ + k0 + tx];   // coalesced read
    __syncthreads();
    #pragma unroll
    for (int i = 0; i < 4; i++)
        g_Mt[(k0 + ty + i*8)*D_ + d0 + tx] = tile[tx][ty + i*8]; // coalesced write
}

// ---------------- L1 NN search (R13's nn8, byte-identical main loop) -------
// 1024 CTAs (128 q-tiles x 8 k-chunks), 256 threads. CTA = 64 q x 64 k.
__global__ void __launch_bounds__(256, 3)
nn8_kernel(const float* __restrict__ H, const float* __restrict__ M) {
    extern __shared__ char smem[];
    float* h_s = (float*)smem;                 // [128][64] plain
    float* m_s = (float*)(smem + 32*1024);     // [128][64] negated

    int tid = threadIdx.x;
    int qt = blockIdx.x & (NQT - 1);
    int kc = blockIdx.x >> 7;
    int q0 = qt * QT;
    int b  = q0 >> 10;
    int t0 = q0 & (T_ - 1);
    int k0 = kc * KCH;

    for (int e = tid; e < (D_*QT)/4; e += 256) {
        int d = e >> 4, q4 = e & 15;
        *(float4*)&h_s[d*QT + q4*4] =
            *(const float4*)&H[b*(D_*T_) + d*T_ + t0 + q4*4];
    }
    for (int e = tid; e < (D_*KCH)/4; e += 256) {
        int d = e >> 4, c4 = e & 15;
        float4 mv = *(const float4*)&M[d*K_ + k0 + c4*4];
        *(float4*)&m_s[d*KCH + c4*4] = make_float4(-mv.x, -mv.y, -mv.z, -mv.w);
    }
    __syncthreads();

    int tk = tid & 15, tq = tid >> 4;   // 16 k-groups x 16 q-groups
    int qq = tq * 4, kk = tk * 4;       // both LDS.128 conflict-free

    unsigned long long a00=0ULL,a01=0ULL,a10=0ULL,a11=0ULL;
    unsigned long long a20=0ULL,a21=0ULL,a30=0ULL,a31=0ULL;

    // 2-stage pipeline: hv/mm hold iteration d; hn/mn prefetch d+1
    float4 hv = *(const float4*)&h_s[qq];
    ulonglong2 mm = *(const ulonglong2*)&m_s[kk];
    #pragma unroll 4
    for (int d = 0; d < D_ - 1; d++) {
        float4 hn = *(const float4*)&h_s[(d+1)*QT + qq];
        ulonglong2 mn = *(const ulonglong2*)&m_s[(d+1)*KCH + kk];
        unsigned long long H0 = dupf(hv.x), H1 = dupf(hv.y);
        unsigned long long H2 = dupf(hv.z), H3 = dupf(hv.w);
        a00 = fadd2u(a00, fadd2u(H0, mm.x) & ABSMASK);
        a01 = fadd2u(a01, fadd2u(H0, mm.y) & ABSMASK);
        a10 = fadd2u(a10, fadd2u(H1, mm.x) & ABSMASK);
        a11 = fadd2u(a11, fadd2u(H1, mm.y) & ABSMASK);
        a20 = fadd2u(a20, fadd2u(H2, mm.x) & ABSMASK);
        a21 = fadd2u(a21, fadd2u(H2, mm.y) & ABSMASK);
        a30 = fadd2u(a30, fadd2u(H3, mm.x) & ABSMASK);
        a31 = fadd2u(a31, fadd2u(H3, mm.y) & ABSMASK);
        hv = hn; mm = mn;
    }
    {
        unsigned long long H0 = dupf(hv.x), H1 = dupf(hv.y);
        unsigned long long H2 = dupf(hv.z), H3 = dupf(hv.w);
        a00 = fadd2u(a00, fadd2u(H0, mm.x) & ABSMASK);
        a01 = fadd2u(a01, fadd2u(H0, mm.y) & ABSMASK);
        a10 = fadd2u(a10, fadd2u(H1, mm.x) & ABSMASK);
        a11 = fadd2u(a11, fadd2u(H1, mm.y) & ABSMASK);
        a20 = fadd2u(a20, fadd2u(H2, mm.x) & ABSMASK);
        a21 = fadd2u(a21, fadd2u(H2, mm.y) & ABSMASK);
        a30 = fadd2u(a30, fadd2u(H3, mm.x) & ABSMASK);
        a31 = fadd2u(a31, fadd2u(H3, mm.y) & ABSMASK);
    }

    // thread-local lexmin per q over its 4 k (ascending k, strict <)
    int kb = k0 + kk;
    float bd[4]; int bi[4];
    unsigned long long p0[4] = {a00, a10, a20, a30};
    unsigned long long p1[4] = {a01, a11, a21, a31};
    #pragma unroll
    for (int iq = 0; iq < 4; iq++) {
        float c0 = __uint_as_float((unsigned)(p0[iq] & 0xffffffffu));
        float c1 = __uint_as_float((unsigned)(p0[iq] >> 32));
        float c2 = __uint_as_float((unsigned)(p1[iq] & 0xffffffffu));
        float c3 = __uint_as_float((unsigned)(p1[iq] >> 32));
        float bdv = c0; int biv = kb;
        if (c1 < bdv) { bdv = c1; biv = kb + 1; }
        if (c2 < bdv) { bdv = c2; biv = kb + 2; }
        if (c3 < bdv) { bdv = c3; biv = kb + 3; }
        bd[iq] = bdv; bi[iq] = biv;
    }

    // lexicographic min across the 16 tk lanes (first-argmin semantics)
    #pragma unroll
    for (int off = 1; off < 16; off <<= 1) {
        #pragma unroll
        for (int iq = 0; iq < 4; iq++) {
            float od = __shfl_xor_sync(0xffffffffu, bd[iq], off);
            int   oi = __shfl_xor_sync(0xffffffffu, bi[iq], off);
            if (od < bd[iq] || (od == bd[iq] && oi < bi[iq])) { bd[iq] = od; bi[iq] = oi; }
        }
    }
    if (tk == 0) {
        #pragma unroll
        for (int iq = 0; iq < 4; iq++) {
            g_bd[kc*Q_ + q0 + qq + iq] = bd[iq];
            g_bi[kc*Q_ + q0 + qq + iq] = bi[iq];
        }
    }
}

// ---------------- combine K-chunks + quantization loss (Mt coalesced) ------
__global__ void nnred_kernel(const float* __restrict__ H) {
    int tid = threadIdx.x;
    int q = blockIdx.x * 256 + tid;
    float bd = g_bd[q]; int bi = g_bi[q];
    #pragma unroll
    for (int c = 1; c < NKC; c++) {
        float dd = g_bd[c*Q_ + q]; int ii = g_bi[c*Q_ + q];
        if (dd < bd) { bd = dd; bi = ii; }   // chunks ascend in k
    }
    int b = q >> 10, t = q & (T_ - 1);
    const float* h = H + b*(D_*T_) + t;
    const float4* mt = (const float4*)&g_Mt[bi*D_];   // contiguous winner row
    float s = 0.f;
    #pragma unroll 8
    for (int d4 = 0; d4 < D_/4; d4++) {
        float4 z = mt[d4];
        float e0 = h[(d4*4    )*T_] - z.x;
        float e1 = h[(d4*4 + 1)*T_] - z.y;
        float e2 = h[(d4*4 + 2)*T_] - z.z;
        float e3 = h[(d4*4 + 3)*T_] - z.w;
        s += e0*e0 + e1*e1 + e2*e2 + e3*e3;
    }
    #pragma unroll
    for (int off = 16; off > 0; off >>= 1) s += __shfl_down_sync(0xffffffffu, s, off);
    __shared__ float red[8];
    int warp = tid >> 5, lane = tid & 31;
    if (lane == 0) red[warp] = s;
    __syncthreads();
    if (tid == 0) {
        float tot = 0.f;
        #pragma unroll
        for (int i = 0; i < 8; i++) tot += red[i];
        atomicAdd(&g_acc[1], tot);
    }
}

// ---------------- dec_e: E = Hdec W^T - X -> g_E (STG), sumE^2 -------------
__global__ void dece_kernel(const float* __restrict__ Hdec, const float* __restrict__ W,
                            const float* __restrict__ X) {
    extern __shared__ char smem[];
    float* hd_s = (float*)smem;                // [16][256]  16KB
    float* w_s  = (float*)(smem + 16384);      // [256][33]  33KB padded
    __shared__ float red[8];

    int tid = threadIdx.x;
    int r0 = blockIdx.x * 16;
    int warp = tid >> 5, lane = tid & 31;

    for (int e = tid; e < C_*F_; e += 256) {
        int c = e >> 8, f = e & 255;
        w_s[f*33 + c] = W[e];
    }
    {
        const float4* src = (const float4*)(Hdec + (size_t)r0 * F_);
        float4* dst = (float4*)hd_s;
        #pragma unroll
        for (int i = 0; i < 4; i++) dst[tid + i*256] = src[tid + i*256];
    }
    __syncthreads();

    float acc0 = 0.f, acc1 = 0.f;
    for (int f = 0; f < F_; f += 4) {
        float w0 = w_s[(f+0)*33 + lane];
        float w1 = w_s[(f+1)*33 + lane];
        float w2 = w_s[(f+2)*33 + lane];
        float w3 = w_s[(f+3)*33 + lane];
        float4 a4 = *(const float4*)&hd_s[(warp*2    )*F_ + f];
        float4 b4 = *(const float4*)&hd_s[(warp*2 + 1)*F_ + f];
        acc0 = fmaf(a4.x, w0, fmaf(a4.y, w1, fmaf(a4.z, w2, fmaf(a4.w, w3, acc0))));
        acc1 = fmaf(b4.x, w0, fmaf(b4.y, w1, fmaf(b4.z, w2, fmaf(b4.w, w3, acc1))));
    }
    float e0 = acc0 - X[(size_t)(r0 + warp*2    )*C_ + lane];
    float e1 = acc1 - X[(size_t)(r0 + warp*2 + 1)*C_ + lane];
    g_E[(r0 + warp*2    )*C_ + lane] = e0;
    g_E[(r0 + warp*2 + 1)*C_ + lane] = e1;
    float s2 = e0*e0 + e1*e1;
    #pragma unroll
    for (int off = 16; off > 0; off >>= 1) s2 += __shfl_down_sync(0xffffffffu, s2, off);
    if (lane == 0) red[warp] = s2;
    __syncthreads();
    if (tid == 0) {
        float tot = 0.f;
        #pragma unroll
        for (int i = 0; i < 8; i++) tot += red[i];
        atomicAdd(&g_acc[0], tot);
    }
}

// ---------------- dec_g: G = E^T @ Hdec (tiled GEMM) + S partials ----------
__global__ void decg_kernel(const float* __restrict__ Hdec) {
    __shared__ float e_s[64*32];    //  8KB
    __shared__ float hd_s[64*64];   // 16KB
    int tid = threadIdx.x;
    int rc = blockIdx.x & 63, ft = blockIdx.x >> 6;
    int r0 = rc * 128, f0 = ft * 64;
    int tc = tid & 15, tf = tid >> 4;

    float ga[8] = {0,0,0,0,0,0,0,0};
    float scol = 0.f;

    for (int sub = 0; sub < 2; sub++) {
        int rr0 = r0 + sub*64;
        __syncthreads();
        {
            const float4* esrc = (const float4*)(g_E + (size_t)rr0 * C_);
            float4* edst = (float4*)e_s;
            edst[tid]       = esrc[tid];
            edst[tid + 256] = esrc[tid + 256];
            const float4* hsrc = (const float4*)(Hdec + (size_t)rr0 * F_ + f0);
            float4* hdst = (float4*)hd_s;
            #pragma unroll
            for (int i = 0; i < 4; i++) {
                int idx = tid + i*256;
                int row = idx >> 4, c4 = idx & 15;
                hdst[row*16 + c4] = hsrc[row*64 + c4];
            }
        }
        __syncthreads();
        #pragma unroll 4
        for (int r = 0; r < 64; r++) {
            float2 ec = *(const float2*)&e_s[r*32 + tc*2];
            float4 hv = *(const float4*)&hd_s[r*64 + tf*4];
            ga[0] += ec.x*hv.x; ga[1] += ec.x*hv.y; ga[2] += ec.x*hv.z; ga[3] += ec.x*hv.w;
            ga[4] += ec.y*hv.x; ga[5] += ec.y*hv.y; ga[6] += ec.y*hv.z; ga[7] += ec.y*hv.w;
        }
        if (tid < 64) {
            #pragma unroll 8
            for (int r = 0; r < 64; r++) scol += hd_s[r*64 + tid];
        }
    }

    if (tid < 64) atomicAdd(&g_S[f0 + tid], scol);
    float* gdst = &g_Gr[(rc & (NREP-1))*C_*F_];
    int c0 = tc*2, fbase = f0 + tf*4;
    #pragma unroll
    for (int j = 0; j < 4; j++) {
        atomicAdd(&gdst[(c0    )*F_ + fbase + j], ga[j]);
        atomicAdd(&gdst[(c0 + 1)*F_ + fbase + j], ga[4 + j]);
    }
}

// ---------------- final scalar assembly (1024 threads, shuffle reduce) -----
__global__ void final_kernel(const float* __restrict__ W, const float* __restrict__ w_d,
                             float* __restrict__ out) {
    __shared__ float4 red4[32];
    int tid = threadIdx.x, lane = tid & 31, warp = tid >> 5;

    float sG = 0.f, sWS = 0.f;
    #pragma unroll
    for (int i = tid; i < C_*F_; i += 1024) {
        float g = g_Gr[i] + g_Gr[C_*F_ + i] + g_Gr[2*C_*F_ + i] + g_Gr[3*C_*F_ + i];
        sG  += g * g;
        sWS += W[i] * g_S[i & 255] * w_d[i >> 8];
    }
    float sS  = (tid < F_) ? g_S[tid]*g_S[tid] : 0.f;
    float wd2 = (tid < C_) ? w_d[tid]*w_d[tid] : 0.f;

    #pragma unroll
    for (int off = 16; off > 0; off >>= 1) {
        sG  += __shfl_down_sync(0xffffffffu, sG,  off);
        sWS += __shfl_down_sync(0xffffffffu, sWS, off);
        sS  += __shfl_down_sync(0xffffffffu, sS,  off);
        wd2 += __shfl_down_sync(0xffffffffu, wd2, off);
    }
    if (lane == 0) red4[warp] = make_float4(sG, sWS, sS, wd2);
    __syncthreads();
    if (warp == 0) {
        float4 v = red4[lane];
        #pragma unroll
        for (int off = 16; off > 0; off >>= 1) {
            v.x += __shfl_down_sync(0xffffffffu, v.x, off);
            v.y += __shfl_down_sync(0xffffffffu, v.y, off);
            v.z += __shfl_down_sync(0xffffffffu, v.z, off);
            v.w += __shfl_down_sync(0xffffffffu, v.w, off);
        }
        if (lane == 0) {
            float loss_rec = g_acc[0] / 262144.f;                 // mean over B*T*C
            float loss_m   = 2.f * g_acc[1] / 1048576.f;          // 2*sum/(B*D*T)
            float normGrec = (2.f / 262144.f) * sqrtf(v.x);       // ||g_rec||_F
            float normGd   = sqrtf(v.w) * sqrtf(v.z) / 8192.f;    // ||g_d||_F (rank-1)
            float lmbda    = normGrec / (normGd + 1e-6f);
            float loss_d   = -v.y / 8192.f;
            out[0] = loss_rec + loss_m + lmbda * loss_d;
        }
    }
}

extern "C" void kernel_launch(void* const* d_in, const int* in_sizes, int n_in,
                              void* d_out, int out_size) {
    const float* X    = (const float*)d_in[0];
    const float* H    = (const float*)d_in[1];
    const float* M    = (const float*)d_in[2];
    const float* Hdec = (const float*)d_in[3];
    const float* W    = (const float*)d_in[4];
    const float* w_d  = (const float*)d_in[5];
    float* out = (float*)d_out;
    (void)in_sizes; (void)n_in; (void)out_size;

    static int init_done = 0;
    static cudaStream_t s2;
    static cudaEvent_t ev_fork, ev_join;
    if (!init_done) {
        cudaFuncSetAttribute(nn8_kernel,  cudaFuncAttributeMaxDynamicSharedMemorySize, 65536);
        cudaFuncSetAttribute(dece_kernel, cudaFuncAttributeMaxDynamicSharedMemorySize, 50176);
        cudaStreamCreateWithFlags(&s2, cudaStreamNonBlocking);
        cudaEventCreateWithFlags(&ev_fork, cudaEventDisableTiming);
        cudaEventCreateWithFlags(&ev_join, cudaEventDisableTiming);
        init_done = 1;
    }

    // fork: decoder chain + M transpose on s2, overlapping nn8 on capture stream
    cudaEventRecord(ev_fork, 0);
    cudaStreamWaitEvent(s2, ev_fork, 0);

    zero_kernel <<<(NREP*C_*F_ + 255)/256, 256, 0, s2>>>();
    mt_kernel   <<<64, 256, 0, s2>>>(M);                   // Mt for nnred's gather
    dece_kernel <<<Q_/16, 256, 50176, s2>>>(Hdec, W, X);   // 512 CTAs
    decg_kernel <<<256, 256, 0, s2>>>(Hdec);               // 256 CTAs

    nn8_kernel  <<<NQT*NKC, 256, 65536>>>(H, M);           // 1024 CTAs: hot kernel

    // join (nnred needs Mt from s2; final needs dec results)
    cudaEventRecord(ev_join, s2);
    cudaStreamWaitEvent(0, ev_join, 0);
    nnred_kernel<<<Q_/256, 256>>>(H);
    final_kernel<<<1, 1024>>>(W, w_d, out);
}